// round 5
// baseline (speedup 1.0000x reference)
#include <cuda_runtime.h>
#include <math.h>

#define B 8
#define S 4096
#define D 1024
#define NEXP 16
#define P 4
#define H 2048
#define NP 64            // NEXP*P
#define TOK (B*S)        // 32768
#define ETOK (B*P)       // 32 tokens per expert
#define LN_EPS 1e-5f

// ---------------- bf16x3 split helpers ---------------------------------------
__device__ __forceinline__ unsigned packbf(float lo, float hi) {
    unsigned r;
    asm("cvt.rn.bf16x2.f32 %0, %1, %2;" : "=r"(r) : "f"(hi), "f"(lo));
    return r;
}
// split (v0,v1) into hi bf16x2 word and residual-lo bf16x2 word
__device__ __forceinline__ void split2(float v0, float v1, unsigned& wh, unsigned& wl) {
    wh = packbf(v0, v1);
    float h0 = __uint_as_float(wh << 16);
    float h1 = __uint_as_float(wh & 0xFFFF0000u);
    wl = packbf(v0 - h0, v1 - h1);
}

__device__ __forceinline__ void mma16816(float c[4],
        unsigned a0, unsigned a1, unsigned a2, unsigned a3,
        unsigned b0, unsigned b1) {
    asm volatile("mma.sync.aligned.m16n8k16.row.col.f32.bf16.bf16.f32 "
        "{%0,%1,%2,%3}, {%4,%5,%6,%7}, {%8,%9}, {%0,%1,%2,%3};"
        : "+f"(c[0]), "+f"(c[1]), "+f"(c[2]), "+f"(c[3])
        : "r"(a0), "r"(a1), "r"(a2), "r"(a3), "r"(b0), "r"(b1));
}
__device__ __forceinline__ void ldsm4(unsigned& r0, unsigned& r1, unsigned& r2, unsigned& r3,
                                      const unsigned* p) {
    unsigned a = (unsigned)__cvta_generic_to_shared(p);
    asm volatile("ldmatrix.sync.aligned.m8n8.x4.shared.b16 {%0,%1,%2,%3}, [%4];"
        : "=r"(r0), "=r"(r1), "=r"(r2), "=r"(r3) : "r"(a));
}
__device__ __forceinline__ void ldsm2(unsigned& r0, unsigned& r1, const unsigned* p) {
    unsigned a = (unsigned)__cvta_generic_to_shared(p);
    asm volatile("ldmatrix.sync.aligned.m8n8.x2.shared.b16 {%0,%1}, [%2];"
        : "=r"(r0), "=r"(r1) : "r"(a));
}

// ---------------- static device scratch --------------------------------------
__device__ float  g_ph[D*NP];
__device__ float  g_wnum[TOK*NP];
__device__ float  g_epart[TOK*P];
__device__ double g_Zd[B*NP];
__device__ float  g_Zf[B*NP];
__device__ double g_Zb[B];
__device__ double g_iZb[B];
__device__ double g_ptn[B*P];
__device__ float  g_shift;
__device__ float  g_xs[B*NP*D];
__device__ float  g_h[NEXP*ETOK*H];
__device__ float  g_r[NEXP*ETOK*D];
__device__ float  g_ys[B*NP*D];
__device__ double g_mi;

// ---------------- init -------------------------------------------------------
__global__ void k_init(const float* __restrict__ task_emb) {
    int idx = blockIdx.x * 256 + threadIdx.x;
    if (idx < B*NP*D) {
        int d  = idx % D;
        int np = (idx / D) % NP;
        g_xs[idx] = task_emb[(np & 3) * D + d];
    }
    if (blockIdx.x < 2) g_Zd[blockIdx.x * 256 + threadIdx.x] = 0.0;
    if (blockIdx.x == 2) {
        if (threadIdx.x < B*P) g_ptn[threadIdx.x] = 0.0;
        if (threadIdx.x == 0)  g_mi = 0.0;
    }
}

// ---------------- normalize phi ----------------------------------------------
__global__ void k_ph(const float* __restrict__ phi, const float* __restrict__ scale) {
    int np = blockIdx.x;
    __shared__ float red[256];
    int t = threadIdx.x;
    float ss = 0.f;
    for (int d = t; d < D; d += 256) { float v = phi[d*NP + np]; ss += v*v; }
    red[t] = ss; __syncthreads();
    for (int o = 128; o > 0; o >>= 1) { if (t < o) red[t] += red[t+o]; __syncthreads(); }
    float inv = scale[0] / fmaxf(sqrtf(red[0]), 1e-12f);
    for (int d = t; d < D; d += 256)
        g_ph[d*NP + np] = phi[d*NP + np] * inv;
    if (np == 0 && t == 0) g_shift = fabsf(scale[0]);
}

// ---------------- logits GEMM + fused softmax epilogues (R3 scalar) ----------
__global__ void k_logits(const float* __restrict__ x, float* __restrict__ out_cmb) {
    __shared__ float x_sm[32*65];
    __shared__ float ph_sm[64*64];
    __shared__ float ssq[32];
    __shared__ float zred[64*8];
    __shared__ float ep_sm[32*4];
    int t = threadIdx.x;
    int tok0 = blockIdx.x * 32;
    int b = tok0 >> 12;
    int ty = t >> 5, tx = t & 31;
    if (t < 32) ssq[t] = 0.f;
    float acc[4][2] = {};
    __syncthreads();
    for (int d0 = 0; d0 < D; d0 += 64) {
        #pragma unroll
        for (int k = 0; k < 8; k++) {
            int i = t + k*256; int tk = i >> 6, dd = i & 63;
            x_sm[tk*65 + dd] = x[(size_t)(tok0+tk)*D + d0 + dd];
        }
        #pragma unroll
        for (int k = 0; k < 16; k++) {
            int i = t + k*256; int dd = i >> 6, np = i & 63;
            ph_sm[dd*64 + np] = g_ph[(d0+dd)*NP + np];
        }
        __syncthreads();
        #pragma unroll
        for (int i = 0; i < 4; i++) {
            int tk = ty*4 + i;
            float v1 = x_sm[tk*65 + tx], v2 = x_sm[tk*65 + tx + 32];
            float s = v1*v1 + v2*v2;
            #pragma unroll
            for (int o = 16; o > 0; o >>= 1) s += __shfl_xor_sync(~0u, s, o);
            if (tx == 0) ssq[tk] += s;
        }
        #pragma unroll 4
        for (int dd = 0; dd < 64; dd++) {
            float p0 = ph_sm[dd*64 + tx];
            float p1 = ph_sm[dd*64 + tx + 32];
            #pragma unroll
            for (int i = 0; i < 4; i++) {
                float xv = x_sm[(ty*4+i)*65 + dd];
                acc[i][0] += xv * p0;
                acc[i][1] += xv * p1;
            }
        }
        __syncthreads();
    }
    if (t < 32) ssq[t] = 1.f / fmaxf(sqrtf(ssq[t]), 1e-12f);
    __syncthreads();
    float shift = g_shift;
    float zsum0 = 0.f, zsum1 = 0.f;
    #pragma unroll
    for (int i = 0; i < 4; i++) {
        int tk = ty*4 + i;
        size_t tok = tok0 + tk;
        float inv = ssq[tk];
        float e0 = expf(acc[i][0]*inv - shift);
        float e1 = expf(acc[i][1]*inv - shift);
        float z = e0 + e1;
        #pragma unroll
        for (int o = 16; o > 0; o >>= 1) z += __shfl_xor_sync(~0u, z, o);
        float izr = 1.f / z;
        out_cmb[tok*NP + tx]      = e0 * izr;
        out_cmb[tok*NP + tx + 32] = e1 * izr;
        g_wnum[tok*NP + tx]      = e0 * inv;
        g_wnum[tok*NP + tx + 32] = e1 * inv;
        float f = e0 + e1;
        f += __shfl_xor_sync(~0u, f, 4);
        f += __shfl_xor_sync(~0u, f, 8);
        f += __shfl_xor_sync(~0u, f, 16);
        if (tx < P) { g_epart[tok*P + tx] = f; ep_sm[tk*P + tx] = f; }
        zsum0 += e0; zsum1 += e1;
    }
    zred[tx*8 + ty] = zsum0;
    zred[(tx+32)*8 + ty] = zsum1;
    __syncthreads();
    if (t < 64) {
        float s = 0.f;
        #pragma unroll
        for (int k = 0; k < 8; k++) s += zred[t*8 + k];
        atomicAdd(&g_Zd[b*NP + t], (double)s);
    }
    if (t < P) {
        float s = 0.f;
        #pragma unroll
        for (int k = 0; k < 32; k++) s += ep_sm[k*P + t];
        atomicAdd(&g_ptn[b*P + t], (double)s);
    }
}

// ---------------- finish Z stats ---------------------------------------------
__global__ void k_zb() {
    int t = threadIdx.x, w = t >> 5, lane = t & 31;
    if (w < B) {
        double z = g_Zd[w*NP + lane] + g_Zd[w*NP + lane + 32];
        #pragma unroll
        for (int o = 16; o > 0; o >>= 1) z += __shfl_xor_sync(~0u, z, o);
        if (lane == 0) { g_Zb[w] = z; g_iZb[w] = 1.0 / z; }
    }
    for (int i = t; i < B*NP; i += 256) g_Zf[i] = (float)(1.0 / g_Zd[i]);
}

// ---------------- xs GEMM (R3 scalar) ----------------------------------------
__global__ void k_xs(const float* __restrict__ x) {
    __shared__ float x_sm[32*128];
    __shared__ float w_sm[32*64];
    __shared__ float rz[64];
    int t = threadIdx.x;
    int b = blockIdx.z, d0 = blockIdx.y * 128, s0 = blockIdx.x * 512;
    if (t < 64) rz[t] = g_Zf[b*NP + t];
    int ty = t >> 4, tx = t & 15;
    float acc[4][8] = {};
    __syncthreads();
    for (int st = 0; st < 512; st += 32) {
        int sbase = b*S + s0 + st;
        #pragma unroll
        for (int k = 0; k < 8; k++) {
            int i = t + k*256; int ss = i >> 6, np = i & 63;
            w_sm[ss*64 + np] = g_wnum[(size_t)(sbase+ss)*NP + np] * rz[np];
        }
        #pragma unroll
        for (int k = 0; k < 16; k++) {
            int i = t + k*256; int ss = i >> 7, dd = i & 127;
            x_sm[ss*128 + dd] = x[(size_t)(sbase+ss)*D + d0 + dd];
        }
        __syncthreads();
        #pragma unroll 2
        for (int ss = 0; ss < 32; ss++) {
            float wf[4], xf[8];
            #pragma unroll
            for (int a = 0; a < 4; a++) wf[a] = w_sm[ss*64 + ty + 16*a];
            #pragma unroll
            for (int j = 0; j < 8; j++) xf[j] = x_sm[ss*128 + tx + 16*j];
            #pragma unroll
            for (int a = 0; a < 4; a++)
                #pragma unroll
                for (int j = 0; j < 8; j++) acc[a][j] += wf[a] * xf[j];
        }
        __syncthreads();
    }
    #pragma unroll
    for (int a = 0; a < 4; a++)
        #pragma unroll
        for (int j = 0; j < 8; j++)
            atomicAdd(&g_xs[(size_t)(b*NP + ty + 16*a)*D + d0 + tx + 16*j], acc[a][j]);
}

// ---------------- FFN1 (bf16x3 mma): h = silu(xs@W1 + b1) --------------------
// M=32 tokens, N-tile 128 h, K=D. smem: A[32][36w], W[128][36w] (hi+lo)
__global__ void k_ffn1(const float* __restrict__ W1, const float* __restrict__ b1) {
    __shared__ unsigned Ah[32*36], Al[32*36];
    __shared__ unsigned Bh[128*36], Bl[128*36];
    int t = threadIdx.x;
    int n = blockIdx.x, h0 = blockIdx.y * 128;
    int w = t >> 5, lane = t & 31;
    float c[2][2][4] = {};
    const float* Wb = W1 + (size_t)n*D*H + h0;
    int am = t >> 3, ak = t & 7;                 // A staging: token, k-octet
    int bbq = am >> 2, ppq = am & 3;
    const float* arow = g_xs + (size_t)(bbq*NP + n*4 + ppq)*D + ak*8;
    int wj = t >> 3, whc = (t & 7) * 16;         // W staging: k-pair, h-seg
    int arow_l = lane & 15;
    int acol_l = (lane & 16) ? 4 : 0;
    int brow_l = lane & 7;
    int bcol_l = (lane & 8) ? 4 : 0;

    for (int d0 = 0; d0 < D; d0 += 64) {
        // stage A (32 x 64)
        {
            float4 v0 = *(const float4*)(arow + d0);
            float4 v1 = *(const float4*)(arow + d0 + 4);
            int base = am*36 + ak*4;
            unsigned hw, lw;
            split2(v0.x, v0.y, hw, lw); Ah[base+0] = hw; Al[base+0] = lw;
            split2(v0.z, v0.w, hw, lw); Ah[base+1] = hw; Al[base+1] = lw;
            split2(v1.x, v1.y, hw, lw); Ah[base+2] = hw; Al[base+2] = lw;
            split2(v1.z, v1.w, hw, lw); Ah[base+3] = hw; Al[base+3] = lw;
        }
        // stage W (64 x 128) transposed-packed: Bw[h][j] = {W[2j][h], W[2j+1][h]}
        {
            const float* wr0 = Wb + (size_t)(d0 + 2*wj)*H + whc;
            const float* wr1 = wr0 + H;
            float v0[16], v1[16];
            #pragma unroll
            for (int q = 0; q < 4; q++) {
                *(float4*)&v0[q*4] = *(const float4*)(wr0 + q*4);
                *(float4*)&v1[q*4] = *(const float4*)(wr1 + q*4);
            }
            #pragma unroll
            for (int q = 0; q < 16; q++) {
                unsigned hw, lw;
                split2(v0[q], v1[q], hw, lw);
                Bh[(whc+q)*36 + wj] = hw;
                Bl[(whc+q)*36 + wj] = lw;
            }
        }
        __syncthreads();
        #pragma unroll
        for (int kk = 0; kk < 4; kk++) {
            unsigned ah[2][4], al[2][4];
            #pragma unroll
            for (int mt = 0; mt < 2; mt++) {
                const unsigned* pa = &Ah[(mt*16 + arow_l)*36 + kk*8 + acol_l];
                ldsm4(ah[mt][0], ah[mt][1], ah[mt][2], ah[mt][3], pa);
                const unsigned* pl = &Al[(mt*16 + arow_l)*36 + kk*8 + acol_l];
                ldsm4(al[mt][0], al[mt][1], al[mt][2], al[mt][3], pl);
            }
            #pragma unroll
            for (int nt = 0; nt < 2; nt++) {
                unsigned bh0, bh1, bl0, bl1;
                const unsigned* pb = &Bh[(w*16 + nt*8 + brow_l)*36 + kk*8 + bcol_l];
                ldsm2(bh0, bh1, pb);
                const unsigned* pbl = &Bl[(w*16 + nt*8 + brow_l)*36 + kk*8 + bcol_l];
                ldsm2(bl0, bl1, pbl);
                #pragma unroll
                for (int mt = 0; mt < 2; mt++) {
                    mma16816(c[mt][nt], ah[mt][0], ah[mt][1], ah[mt][2], ah[mt][3], bh0, bh1);
                    mma16816(c[mt][nt], ah[mt][0], ah[mt][1], ah[mt][2], ah[mt][3], bl0, bl1);
                    mma16816(c[mt][nt], al[mt][0], al[mt][1], al[mt][2], al[mt][3], bh0, bh1);
                }
            }
        }
        __syncthreads();
    }
    int gr = lane >> 2, tc = lane & 3;
    #pragma unroll
    for (int mt = 0; mt < 2; mt++) {
        #pragma unroll
        for (int nt = 0; nt < 2; nt++) {
            int hc = h0 + w*16 + nt*8 + tc*2;
            float bv0 = b1[n*H + hc], bv1 = b1[n*H + hc + 1];
            int tk0 = mt*16 + gr, tk1 = tk0 + 8;
            float o0 = c[mt][nt][0] + bv0, o1 = c[mt][nt][1] + bv1;
            float o2 = c[mt][nt][2] + bv0, o3 = c[mt][nt][3] + bv1;
            o0 = o0 / (1.f + expf(-o0)); o1 = o1 / (1.f + expf(-o1));
            o2 = o2 / (1.f + expf(-o2)); o3 = o3 / (1.f + expf(-o3));
            *(float2*)&g_h[((size_t)n*ETOK + tk0)*H + hc] = make_float2(o0, o1);
            *(float2*)&g_h[((size_t)n*ETOK + tk1)*H + hc] = make_float2(o2, o3);
        }
    }
}

// ---------------- FFN2 (bf16x3 mma): r = xs + h@W2 + b2 ----------------------
__global__ void k_ffn2(const float* __restrict__ W2, const float* __restrict__ b2) {
    __shared__ unsigned Ah[32*36], Al[32*36];
    __shared__ unsigned Bh[128*36], Bl[128*36];
    int t = threadIdx.x;
    int n = blockIdx.x, d0 = blockIdx.y * 128;
    int w = t >> 5, lane = t & 31;
    float c[2][2][4] = {};
    const float* Wb = W2 + (size_t)n*H*D + d0;
    int am = t >> 3, ak = t & 7;
    const float* arow = g_h + ((size_t)n*ETOK + am)*H + ak*8;
    int wj = t >> 3, wdc = (t & 7) * 16;
    int arow_l = lane & 15;
    int acol_l = (lane & 16) ? 4 : 0;
    int brow_l = lane & 7;
    int bcol_l = (lane & 8) ? 4 : 0;

    for (int h0 = 0; h0 < H; h0 += 64) {
        {
            float4 v0 = *(const float4*)(arow + h0);
            float4 v1 = *(const float4*)(arow + h0 + 4);
            int base = am*36 + ak*4;
            unsigned hw, lw;
            split2(v0.x, v0.y, hw, lw); Ah[base+0] = hw; Al[base+0] = lw;
            split2(v0.z, v0.w, hw, lw); Ah[base+1] = hw; Al[base+1] = lw;
            split2(v1.x, v1.y, hw, lw); Ah[base+2] = hw; Al[base+2] = lw;
            split2(v1.z, v1.w, hw, lw); Ah[base+3] = hw; Al[base+3] = lw;
        }
        {
            const float* wr0 = Wb + (size_t)(h0 + 2*wj)*D + wdc;
            const float* wr1 = wr0 + D;
            float v0[16], v1[16];
            #pragma unroll
            for (int q = 0; q < 4; q++) {
                *(float4*)&v0[q*4] = *(const float4*)(wr0 + q*4);
                *(float4*)&v1[q*4] = *(const float4*)(wr1 + q*4);
            }
            #pragma unroll
            for (int q = 0; q < 16; q++) {
                unsigned hw, lw;
                split2(v0[q], v1[q], hw, lw);
                Bh[(wdc+q)*36 + wj] = hw;
                Bl[(wdc+q)*36 + wj] = lw;
            }
        }
        __syncthreads();
        #pragma unroll
        for (int kk = 0; kk < 4; kk++) {
            unsigned ah[2][4], al[2][4];
            #pragma unroll
            for (int mt = 0; mt < 2; mt++) {
                const unsigned* pa = &Ah[(mt*16 + arow_l)*36 + kk*8 + acol_l];
                ldsm4(ah[mt][0], ah[mt][1], ah[mt][2], ah[mt][3], pa);
                const unsigned* pl = &Al[(mt*16 + arow_l)*36 + kk*8 + acol_l];
                ldsm4(al[mt][0], al[mt][1], al[mt][2], al[mt][3], pl);
            }
            #pragma unroll
            for (int nt = 0; nt < 2; nt++) {
                unsigned bh0, bh1, bl0, bl1;
                const unsigned* pb = &Bh[(w*16 + nt*8 + brow_l)*36 + kk*8 + bcol_l];
                ldsm2(bh0, bh1, pb);
                const unsigned* pbl = &Bl[(w*16 + nt*8 + brow_l)*36 + kk*8 + bcol_l];
                ldsm2(bl0, bl1, pbl);
                #pragma unroll
                for (int mt = 0; mt < 2; mt++) {
                    mma16816(c[mt][nt], ah[mt][0], ah[mt][1], ah[mt][2], ah[mt][3], bh0, bh1);
                    mma16816(c[mt][nt], ah[mt][0], ah[mt][1], ah[mt][2], ah[mt][3], bl0, bl1);
                    mma16816(c[mt][nt], al[mt][0], al[mt][1], al[mt][2], al[mt][3], bh0, bh1);
                }
            }
        }
        __syncthreads();
    }
    int gr = lane >> 2, tc = lane & 3;
    #pragma unroll
    for (int mt = 0; mt < 2; mt++) {
        #pragma unroll
        for (int nt = 0; nt < 2; nt++) {
            int dc = d0 + w*16 + nt*8 + tc*2;
            float bv0 = b2[n*D + dc], bv1 = b2[n*D + dc + 1];
            #pragma unroll
            for (int half = 0; half < 2; half++) {
                int tk = mt*16 + gr + half*8;
                int bb = tk >> 2, pp = tk & 3;
                float2 xsv = *(const float2*)&g_xs[(size_t)(bb*NP + n*4 + pp)*D + dc];
                float r0 = xsv.x + c[mt][nt][half*2+0] + bv0;
                float r1 = xsv.y + c[mt][nt][half*2+1] + bv1;
                *(float2*)&g_r[((size_t)n*ETOK + tk)*D + dc] = make_float2(r0, r1);
            }
        }
    }
}

// ---------------- LayerNorm per expert-token row -----------------------------
__global__ void k_ln(const float* __restrict__ ln_g, const float* __restrict__ ln_b) {
    int row = blockIdx.x;
    int n = row >> 5, tk = row & 31;
    int t = threadIdx.x;
    const float* r = g_r + (size_t)row*D;
    float v[4]; float s = 0.f, s2 = 0.f;
    #pragma unroll
    for (int k = 0; k < 4; k++) { v[k] = r[t + k*256]; s += v[k]; s2 += v[k]*v[k]; }
    __shared__ float rs[256], rs2[256];
    rs[t] = s; rs2[t] = s2; __syncthreads();
    for (int o = 128; o > 0; o >>= 1) {
        if (t < o) { rs[t] += rs[t+o]; rs2[t] += rs2[t+o]; }
        __syncthreads();
    }
    float mu = rs[0] / D;
    float var = rs2[0] / D - mu*mu;
    float rstd = rsqrtf(var + LN_EPS);
    int bb = tk >> 2, pp = tk & 3;
    float* o = g_ys + (size_t)(bb*NP + n*4 + pp)*D;
    #pragma unroll
    for (int k = 0; k < 4; k++) {
        int d = t + k*256;
        o[d] = (v[k] - mu) * rstd * ln_g[n*D + d] + ln_b[n*D + d];
    }
}

// ---------------- combine (bf16x3 mma): out[p,b,s,d] = sum_n ys·cmb ----------
// per (b,p): A = cmb[s][n] (M=S, K=16), B = ys[n][d] (N=D). one k-step.
__global__ void k_combine(const float* __restrict__ cmb, float* __restrict__ out) {
    __shared__ unsigned Ah[128*12], Al[128*12];
    __shared__ unsigned Bh[128*12], Bl[128*12];
    int t = threadIdx.x;
    int s0 = blockIdx.x * 128, d0 = blockIdx.y * 128;
    int bp = blockIdx.z; int b = bp >> 2, p = bp & 3;
    int w = t >> 5, lane = t & 31;
    // stage A: Aw[s][j] = {cmb[s][(2j)*4+p], cmb[s][(2j+1)*4+p]}
    #pragma unroll
    for (int it = 0; it < 4; it++) {
        int idx = t + it*256;
        int s = idx >> 3, j = idx & 7;
        const float* cp = cmb + (size_t)(b*S + s0 + s)*NP + j*8 + p;
        unsigned hw, lw;
        split2(cp[0], cp[4], hw, lw);
        Ah[s*12 + j] = hw; Al[s*12 + j] = lw;
    }
    // stage B: Bw[dd][j] = {ys[2j][dd], ys[2j+1][dd]}
    #pragma unroll
    for (int it = 0; it < 4; it++) {
        int idx = t + it*256;
        int dd = idx & 127, j = idx >> 7;
        const float* yp = g_ys + (size_t)(b*NP + 8*j + p)*D + d0 + dd;
        unsigned hw, lw;
        split2(yp[0], yp[4*D], hw, lw);
        Bh[dd*12 + j] = hw; Bl[dd*12 + j] = lw;
    }
    __syncthreads();
    int arow_l = lane & 15;
    int acol_l = (lane & 16) ? 4 : 0;
    int brow_l = lane & 7;
    int bcol_l = (lane & 8) ? 4 : 0;
    unsigned a0h, a1h, a2h, a3h, a0l, a1l, a2l, a3l;
    ldsm4(a0h, a1h, a2h, a3h, &Ah[(w*16 + arow_l)*12 + acol_l]);
    ldsm4(a0l, a1l, a2l, a3l, &Al[(w*16 + arow_l)*12 + acol_l]);
    float acc[16][4];
    #pragma unroll
    for (int nt = 0; nt < 16; nt++) { acc[nt][0]=0.f; acc[nt][1]=0.f; acc[nt][2]=0.f; acc[nt][3]=0.f; }
    #pragma unroll
    for (int nt = 0; nt < 16; nt++) {
        unsigned bh0, bh1, bl0, bl1;
        ldsm2(bh0, bh1, &Bh[(nt*8 + brow_l)*12 + bcol_l]);
        ldsm2(bl0, bl1, &Bl[(nt*8 + brow_l)*12 + bcol_l]);
        mma16816(acc[nt], a0h, a1h, a2h, a3h, bh0, bh1);
        mma16816(acc[nt], a0h, a1h, a2h, a3h, bl0, bl1);
        mma16816(acc[nt], a0l, a1l, a2l, a3l, bh0, bh1);
    }
    int gr = lane >> 2, tc = lane & 3;
    size_t obase = ((size_t)(p*B + b)*S + s0 + w*16)*D + d0;
    #pragma unroll
    for (int nt = 0; nt < 16; nt++) {
        int col = nt*8 + tc*2;
        *(float2*)(out + obase + (size_t)gr*D + col)     = make_float2(acc[nt][0], acc[nt][1]);
        *(float2*)(out + obase + (size_t)(gr+8)*D + col) = make_float2(acc[nt][2], acc[nt][3]);
    }
}

// ---------------- mutual info loss -------------------------------------------
__global__ void k_mi() {
    __shared__ double red[256];
    int t = threadIdx.x;
    int tok = blockIdx.x * 256 + t;
    int b = tok >> 12;
    double iZb = g_iZb[b];
    double pv[P]; double pm = 0.0;
    #pragma unroll
    for (int p = 0; p < P; p++) { pv[p] = (double)g_epart[tok*P + p] * iZb; pm += pv[p]; }
    double term = 0.0;
    #pragma unroll
    for (int p = 0; p < P; p++) {
        double pt_p = g_ptn[b*P + p] * iZb;
        double ratio = pv[p] / (pm * pt_p) + 1e-10;
        term += pv[p] * log(ratio);
    }
    red[t] = term; __syncthreads();
    for (int o = 128; o > 0; o >>= 1) { if (t < o) red[t] += red[t+o]; __syncthreads(); }
    if (t == 0) atomicAdd(&g_mi, red[0]);
}

__global__ void k_fin(float* __restrict__ out_mi) {
    out_mi[0] = (float)(-g_mi);
}

// ---------------- launch -----------------------------------------------------
extern "C" void kernel_launch(void* const* d_in, const int* in_sizes, int n_in,
                              void* d_out, int out_size) {
    const float* x        = (const float*)d_in[0];
    const float* phi      = (const float*)d_in[1];
    const float* scale    = (const float*)d_in[2];
    const float* task_emb = (const float*)d_in[3];
    const float* W1       = (const float*)d_in[4];
    const float* b1       = (const float*)d_in[5];
    const float* W2       = (const float*)d_in[6];
    const float* b2       = (const float*)d_in[7];
    const float* ln_g     = (const float*)d_in[8];
    const float* ln_b     = (const float*)d_in[9];
    float* out = (float*)d_out;
    float* out_cmb = out + (size_t)P*B*S*D;
    float* out_mi  = out_cmb + (size_t)B*S*NP;

    k_init<<<2048, 256>>>(task_emb);
    k_ph<<<NP, 256>>>(phi, scale);
    k_logits<<<TOK/32, 256>>>(x, out_cmb);
    k_zb<<<1, 256>>>();
    k_xs<<<dim3(8, 8, B), 256>>>(x);
    k_ffn1<<<dim3(NEXP, H/128), 256>>>(W1, b1);
    k_ffn2<<<dim3(NEXP, D/128), 256>>>(W2, b2);
    k_ln<<<NEXP*ETOK, 256>>>(ln_g, ln_b);
    k_combine<<<dim3(S/128, D/128, B*P), 256>>>(out_cmb, out);
    k_mi<<<TOK/256, 256>>>();
    k_fin<<<1, 1>>>(out_mi);
}